// round 16
// baseline (speedup 1.0000x reference)
#include <cuda_runtime.h>
#include <cuda_fp16.h>
#include <cstdint>
#include <cstddef>

#define B_  256
#define T_  512
#define I_  512
#define H_  1024
#define HB_ 256
#define O_  128
#define M_  (B_ * T_)     // 131072

// ---------------------------------------------------------------------------
// Scratch (device globals; allocation is forbidden)
// ---------------------------------------------------------------------------
__device__ __align__(1024) __half g_xh[(size_t)M_ * I_];      // 128 MB each
__device__ __align__(1024) __half g_xm[(size_t)M_ * I_];
__device__ __align__(1024) __half g_wh[H_ * I_];              // 1 MB each, [n][k]
__device__ __align__(1024) __half g_wm[H_ * I_];

// ---------------------------------------------------------------------------
// Prep kernel: one launch does x-split, W-split, and out-zeroing.
// blocks [0, XBLKS)            : x split (fp16 two-term: h=fl16(x), m=fl16(x-h))
// blocks [XBLKS, XBLKS+WBLKS)  : W split (transposed to [n][k])
// blocks [XBLKS+WBLKS, +ZBLKS) : zero out
// ---------------------------------------------------------------------------
#define XBLKS (M_ * I_ / 4 / 256)   // 65536
#define WBLKS (H_ * I_ / 256)       // 2048
#define ZBLKS (B_ * O_ / 256)       // 128

__global__ __launch_bounds__(256)
void prep_kernel(const float* __restrict__ x,
                 const float* __restrict__ Wb,
                 float* __restrict__ out) {
    const int bid = blockIdx.x;
    const int tid = threadIdx.x;

    if (bid < XBLKS) {
        size_t i = (size_t)bid * 256 + tid;   // float4 index
        float4 v = reinterpret_cast<const float4*>(x)[i];
        float f[4] = {v.x, v.y, v.z, v.w};
        __half h[4], m4[4];
#pragma unroll
        for (int j = 0; j < 4; j++) {
            float a = f[j];
            __half hh = __float2half_rn(a);
            float r = a - __half2float(hh);
            h[j] = hh;
            m4[j] = __float2half_rn(r);
        }
        __half2* ph = reinterpret_cast<__half2*>(g_xh);
        __half2* pm = reinterpret_cast<__half2*>(g_xm);
        ph[2 * i]     = __half2(h[0], h[1]);
        ph[2 * i + 1] = __half2(h[2], h[3]);
        pm[2 * i]     = __half2(m4[0], m4[1]);
        pm[2 * i + 1] = __half2(m4[2], m4[3]);
    } else if (bid < XBLKS + WBLKS) {
        int idx = (bid - XBLKS) * 256 + tid;   // n*I + k
        int n = idx >> 9;
        int k = idx & (I_ - 1);
        int nb = n >> 8;
        int hb = n & (HB_ - 1);
        float a = Wb[((size_t)nb * I_ + k) * HB_ + hb];
        __half hh = __float2half_rn(a);
        float r = a - __half2float(hh);
        g_wh[idx] = hh;
        g_wm[idx] = __float2half_rn(r);
    } else {
        out[(bid - XBLKS - WBLKS) * 256 + tid] = 0.f;
    }
}

// ---------------------------------------------------------------------------
// FUSED GEMM + LIF + OUTPUT kernel, continuous cp.async ring.
// grid = (8 h-tiles, 256 batches). CTA tile 128(t)x128(h), warp 64x32,
// K-chunk 32, 3-stage ring, 2 CTAs/SM. At each tile boundary the freed stage
// holds the u-tile in two 64-row halves while next-tile chunks stream in.
// Final epilogue: out[b, :] += acc_tile @ Wout[n0:n0+128, :] via atomics.
// ---------------------------------------------------------------------------
#define KC 32
#define NGC 64                     // global chunks = 4 tiles * 16
#define PART_BYTES (128 * KC * 2)  // 8192 (128 rows x 64B)
#define STAGE_BYTES (4 * PART_BYTES)   // 32768: 2 A parts + 2 B parts
#define SMEM_GEMM (3 * STAGE_BYTES)    // 98304 -> 2 CTAs/SM

__device__ __forceinline__ uint32_t smem_u32(const void* p) {
    uint32_t a;
    asm("{ .reg .u64 t; cvta.to.shared.u64 t, %1; cvt.u32.u64 %0, t; }"
        : "=r"(a) : "l"(p));
    return a;
}
// 64B-row swizzle: row r (0..127), 16B slot h (0..3) — conflict-free per phase
__device__ __forceinline__ uint32_t sw64(int r, int h) {
    return (uint32_t)(r * 64 + ((h ^ ((r >> 1) & 3)) << 4));
}
// u-buffer rotation: row r (0..63), float column c (0..127) -> float index
__device__ __forceinline__ int urot(int c, int r) {
    return r * 128 + ((c + ((r & 31) << 2)) & 127);
}

#define CP16(dst, src) \
    asm volatile("cp.async.cg.shared.global [%0], [%1], 16;" \
                 :: "r"(dst), "l"(src))
#define CPCOMMIT() asm volatile("cp.async.commit_group;" ::: "memory")
#define CPWAIT(n)  asm volatile("cp.async.wait_group %0;" :: "n"(n) : "memory")

#define LDSM4(r0, r1, r2, r3, addr) \
    asm volatile("ldmatrix.sync.aligned.m8n8.x4.shared.b16 {%0,%1,%2,%3}, [%4];" \
                 : "=r"(r0), "=r"(r1), "=r"(r2), "=r"(r3) : "r"(addr))

#define MMA16816(d, a, b) \
    asm volatile("mma.sync.aligned.m16n8k16.row.col.f32.f16.f16.f32 " \
                 "{%0,%1,%2,%3}, {%4,%5,%6,%7}, {%8,%9}, {%0,%1,%2,%3};" \
                 : "+f"((d)[0]), "+f"((d)[1]), "+f"((d)[2]), "+f"((d)[3]) \
                 : "r"((a)[0]), "r"((a)[1]), "r"((a)[2]), "r"((a)[3]), \
                   "r"((b)[0]), "r"((b)[1]))

// LIF step. sneg carries -V_TH*s_prev in {0.0f, -1.0f}.
// spike: v > 1  <=>  signbit(1 - v); v==1 gives +0 -> no spike (strict >).
// Operand values identical to the predicate version -> bitwise-same results.
#define LIF_STEP(U)                                                           \
    {                                                                         \
        st_d = fmaf(c_beta, st_d, c_omb * (U));                               \
        st_v = fmaf(c_alpha, st_v, fmaf(c_oma, st_d, sneg));                  \
        sneg = __int_as_float((__float_as_int(1.0f - st_v) >> 31)             \
                              & 0xBF800000);                                  \
    }

__global__ __launch_bounds__(256, 2)
void gemm_lif_kernel(const float* __restrict__ v0,
                     const float* __restrict__ tau_n,
                     const float* __restrict__ tau_m,
                     const float* __restrict__ Wout,
                     const float* __restrict__ bout,
                     float* __restrict__ out) {
    extern __shared__ char smem[];
    const uint32_t sb = smem_u32(smem);

    const int tid  = threadIdx.x;
    const int wid  = tid >> 5;
    const int lane = tid & 31;
    const int n0 = blockIdx.x * 128;   // h-tile (8) — fast dim: CTAs share x[b] in L2
    const int b  = blockIdx.y;         // batch (256)

    const int wm_off = (wid & 1) * 64;
    const int wn_off = (wid >> 1) * 32;

    const __half* XP[2] = {g_xh, g_xm};
    const __half* WP[2] = {g_wh, g_wm};

    // ---- persistent LIF state (threads 0..127; one h column each) ----
    float st_d = 0.f, st_v = 0.f, sneg = 0.f, st_acc = 0.f;
    float c_beta = 0.f, c_omb = 0.f, c_alpha = 0.f, c_oma = 0.f;
    if (tid < 128) {
        const int hg = n0 + tid;
        c_beta  = 1.f / (1.f + expf(-tau_n[hg]));
        c_alpha = 1.f / (1.f + expf(-tau_m[hg]));
        c_omb   = 1.f - c_beta;
        c_oma   = 1.f - c_alpha;
        st_v    = v0[b * H_ + hg];
    }

    // cp.async mapping: 128 rows x 4 sixteen-byte slots per part, 2 units/thread
    const int ldr = tid >> 2;          // row 0..63 (unit 0); +64 for unit 1
    const int ldh = tid & 3;           // slot 0..3
    const uint32_t dst0 = sw64(ldr, ldh);           // unit 1: +4096
    const size_t srcA0 = (size_t)(b * T_ + ldr) * I_ + ldh * 8;
    const size_t srcB  = (size_t)(n0 + ldr) * I_ + ldh * 8;

    const int arow = wm_off + (lane & 15);
    const int ahl  = (lane >> 4) & 1;               // k 16B-slot low bit
    const int brow = wn_off + (lane & 7) + ((lane >> 4) << 3);
    const int bhl  = (lane >> 3) & 1;

    const int g  = lane >> 2;
    const int tq = lane & 3;

    // load chunk gc into stage gc%3 (A tile depends on gc's t-tile)
    auto load_chunk = [&](int gc) {
        const uint32_t base = sb + (gc % 3) * STAGE_BYTES;
        const size_t sA = srcA0 + (size_t)(gc >> 4) * 128 * I_ + (gc & 15) * KC;
        const size_t sB = srcB + (gc & 15) * KC;
#pragma unroll
        for (int p = 0; p < 2; p++) {
            CP16(base + p * PART_BYTES + dst0,        XP[p] + sA);
            CP16(base + p * PART_BYTES + dst0 + 4096, XP[p] + sA + (size_t)64 * I_);
        }
#pragma unroll
        for (int p = 0; p < 2; p++) {
            CP16(base + (2 + p) * PART_BYTES + dst0,        WP[p] + sB);
            CP16(base + (2 + p) * PART_BYTES + dst0 + 4096, WP[p] + sB + (size_t)64 * I_);
        }
    };

    load_chunk(0); CPCOMMIT();
    load_chunk(1); CPCOMMIT();

    float acc[4][4][4];
#pragma unroll
    for (int i = 0; i < 4; i++)
#pragma unroll
        for (int j = 0; j < 4; j++)
#pragma unroll
            for (int q = 0; q < 4; q++) acc[i][j][q] = 0.f;

    for (int gc = 0; gc < NGC; gc++) {
        if (gc < NGC - 1) { CPWAIT(1); } else { CPWAIT(0); }
        __syncthreads();
        if (gc + 2 < NGC) { load_chunk(gc + 2); CPCOMMIT(); }

        const uint32_t aBase = sb + (gc % 3) * STAGE_BYTES;
        const uint32_t bBase = aBase + 2 * PART_BYTES;

#pragma unroll
        for (int kk2 = 0; kk2 < 2; kk2++) {         // two k16 sub-steps
            const int ha = kk2 * 2 + ahl;
            const int hb = kk2 * 2 + bhl;

            uint32_t bf[2][4][2];
#pragma unroll
            for (int p = 0; p < 2; p++)
#pragma unroll
                for (int j2 = 0; j2 < 2; j2++) {
                    uint32_t r0, r1, r2, r3;
                    LDSM4(r0, r1, r2, r3,
                          bBase + p * PART_BYTES + sw64(brow + 16 * j2, hb));
                    bf[p][2 * j2][0] = r0;     bf[p][2 * j2][1] = r1;
                    bf[p][2 * j2 + 1][0] = r2; bf[p][2 * j2 + 1][1] = r3;
                }

            // A high part: hh + hm (one A-part live at a time: no spills)
            {
                uint32_t af[4][4];
#pragma unroll
                for (int i = 0; i < 4; i++)
                    LDSM4(af[i][0], af[i][1], af[i][2], af[i][3],
                          aBase + sw64(arow + 16 * i, ha));
#pragma unroll
                for (int i = 0; i < 4; i++)
#pragma unroll
                    for (int j = 0; j < 4; j++)
                        MMA16816(acc[i][j], af[i], bf[0][j]);
#pragma unroll
                for (int i = 0; i < 4; i++)
#pragma unroll
                    for (int j = 0; j < 4; j++)
                        MMA16816(acc[i][j], af[i], bf[1][j]);
            }
            // A mid part: mh
            {
                uint32_t af[4][4];
#pragma unroll
                for (int i = 0; i < 4; i++)
                    LDSM4(af[i][0], af[i][1], af[i][2], af[i][3],
                          aBase + PART_BYTES + sw64(arow + 16 * i, ha));
#pragma unroll
                for (int i = 0; i < 4; i++)
#pragma unroll
                    for (int j = 0; j < 4; j++)
                        MMA16816(acc[i][j], af[i], bf[0][j]);
            }
        }

        // ---------------- tile boundary: dump + LIF in the freed stage -------
        if ((gc & 15) == 15) {
            const int mt = gc >> 4;
            float* u_s = reinterpret_cast<float*>(smem + (gc % 3) * STAGE_BYTES);

            __syncthreads();   // all warps done reading the freed stage

#pragma unroll
            for (int half = 0; half < 2; half++) {
                // dump: warps whose rows fall in this half (wm_off==64*half)
                if (wm_off == half * 64) {
#pragma unroll
                    for (int i = 0; i < 4; i++)
#pragma unroll
                        for (int h2 = 0; h2 < 2; h2++) {
                            int r = 16 * i + 8 * h2 + g;        // row within half
#pragma unroll
                            for (int j = 0; j < 4; j++) {
                                int col = wn_off + 2 * tq + 8 * j;
                                float2 v = make_float2(acc[i][j][2 * h2],
                                                       acc[i][j][2 * h2 + 1]);
                                *reinterpret_cast<float2*>(u_s + urot(col, r)) = v;
                            }
                        }
                }
                __syncthreads();

                // LIF over this half's 64 timesteps (short-chain sign trick)
                if (tid < 128) {
                    if (mt < 2) {
#pragma unroll 4
                        for (int tl = 0; tl < 64; tl++) {
                            float u = u_s[urot(tid, tl)];
                            LIF_STEP(u);
                        }
                    } else {
#pragma unroll 4
                        for (int tl = 0; tl < 64; tl++) {
                            float u = u_s[urot(tid, tl)];
                            LIF_STEP(u);
                            st_acc -= sneg;         // acc += s
                        }
                    }
                }
                __syncthreads();   // half A: reads done before half-B dump;
                                   // half B: stage free before future prefetch
            }

            // reset accumulators for the next t-tile
#pragma unroll
            for (int i = 0; i < 4; i++)
#pragma unroll
                for (int j = 0; j < 4; j++)
#pragma unroll
                    for (int q = 0; q < 4; q++) acc[i][j][q] = 0.f;
        }
    }

    // ---------------- fused output epilogue ----------------
    // out[b, o] += sum_h st_acc[h] * Wout[n0+h, o]  (+ bias from h-tile 0)
    {
        float* sacc = reinterpret_cast<float*>(smem);
        if (tid < 128) sacc[tid] = st_acc;
        __syncthreads();
        if (tid < 128) {
            const float* wp = Wout + (size_t)n0 * O_ + tid;
            float sum = (blockIdx.x == 0) ? bout[tid] : 0.f;
#pragma unroll 8
            for (int h = 0; h < 128; h++)
                sum = fmaf(sacc[h], __ldg(wp + h * O_), sum);
            atomicAdd(out + b * O_ + tid, sum);
        }
    }
}

// ---------------------------------------------------------------------------
extern "C" void kernel_launch(void* const* d_in, const int* in_sizes, int n_in,
                              void* d_out, int out_size) {
    const float* x     = (const float*)d_in[0];
    const float* v0    = (const float*)d_in[1];
    const float* Wb    = (const float*)d_in[2];
    const float* tau_n = (const float*)d_in[3];
    const float* tau_m = (const float*)d_in[4];
    const float* Wout  = (const float*)d_in[5];
    const float* bout  = (const float*)d_in[6];
    float* out = (float*)d_out;
    (void)in_sizes; (void)n_in; (void)out_size;

    static bool attr_set = false;
    if (!attr_set) {
        cudaFuncSetAttribute(gemm_lif_kernel,
                             cudaFuncAttributeMaxDynamicSharedMemorySize,
                             SMEM_GEMM);
        attr_set = true;
    }

    prep_kernel<<<XBLKS + WBLKS + ZBLKS, 256>>>(x, Wb, out);   // launch 0

    dim3 ggrid(H_ / 128, B_);   // (8, 256)
    gemm_lif_kernel<<<ggrid, 256, SMEM_GEMM>>>(v0, tau_n, tau_m,
                                               Wout, bout, out);  // launch 1
}

// round 17
// speedup vs baseline: 1.0122x; 1.0122x over previous
#include <cuda_runtime.h>
#include <cuda_fp16.h>
#include <cstdint>
#include <cstddef>

#define B_  256
#define T_  512
#define I_  512
#define H_  1024
#define HB_ 256
#define O_  128
#define M_  (B_ * T_)     // 131072

// ---------------------------------------------------------------------------
// Scratch (device globals; allocation is forbidden)
// ---------------------------------------------------------------------------
__device__ __align__(1024) __half g_xh[(size_t)M_ * I_];      // 128 MB each
__device__ __align__(1024) __half g_xm[(size_t)M_ * I_];
__device__ __align__(1024) __half g_wh[H_ * I_];              // 1 MB each, [n][k]
__device__ __align__(1024) __half g_wm[H_ * I_];

// ---------------------------------------------------------------------------
// Prep kernel: one launch does x-split, W-split, and out-zeroing.
// ---------------------------------------------------------------------------
#define XBLKS (M_ * I_ / 4 / 256)   // 65536
#define WBLKS (H_ * I_ / 256)       // 2048
#define ZBLKS (B_ * O_ / 256)       // 128

__global__ __launch_bounds__(256)
void prep_kernel(const float* __restrict__ x,
                 const float* __restrict__ Wb,
                 float* __restrict__ out) {
    const int bid = blockIdx.x;
    const int tid = threadIdx.x;

    if (bid < XBLKS) {
        size_t i = (size_t)bid * 256 + tid;   // float4 index
        float4 v = reinterpret_cast<const float4*>(x)[i];
        float f[4] = {v.x, v.y, v.z, v.w};
        __half h[4], m4[4];
#pragma unroll
        for (int j = 0; j < 4; j++) {
            float a = f[j];
            __half hh = __float2half_rn(a);
            float r = a - __half2float(hh);
            h[j] = hh;
            m4[j] = __float2half_rn(r);
        }
        __half2* ph = reinterpret_cast<__half2*>(g_xh);
        __half2* pm = reinterpret_cast<__half2*>(g_xm);
        ph[2 * i]     = __half2(h[0], h[1]);
        ph[2 * i + 1] = __half2(h[2], h[3]);
        pm[2 * i]     = __half2(m4[0], m4[1]);
        pm[2 * i + 1] = __half2(m4[2], m4[3]);
    } else if (bid < XBLKS + WBLKS) {
        int idx = (bid - XBLKS) * 256 + tid;   // n*I + k
        int n = idx >> 9;
        int k = idx & (I_ - 1);
        int nb = n >> 8;
        int hb = n & (HB_ - 1);
        float a = Wb[((size_t)nb * I_ + k) * HB_ + hb];
        __half hh = __float2half_rn(a);
        float r = a - __half2float(hh);
        g_wh[idx] = hh;
        g_wm[idx] = __float2half_rn(r);
    } else {
        out[(bid - XBLKS - WBLKS) * 256 + tid] = 0.f;
    }
}

// ---------------------------------------------------------------------------
// FUSED GEMM + LIF + OUTPUT kernel, continuous cp.async ring,
// rotating stage registers + incremental offsets (no per-chunk %, *, >>).
// grid = (8 h-tiles, 256 batches). CTA tile 128(t)x128(h), warp 64x32,
// K-chunk 32, 3-stage ring, 2 CTAs/SM.
// ---------------------------------------------------------------------------
#define KC 32
#define NGC 64                     // global chunks = 4 tiles * 16
#define PART_BYTES (128 * KC * 2)  // 8192 (128 rows x 64B)
#define STAGE_BYTES (4 * PART_BYTES)   // 32768: 2 A parts + 2 B parts
#define SMEM_GEMM (3 * STAGE_BYTES)    // 98304 -> 2 CTAs/SM

__device__ __forceinline__ uint32_t smem_u32(const void* p) {
    uint32_t a;
    asm("{ .reg .u64 t; cvta.to.shared.u64 t, %1; cvt.u32.u64 %0, t; }"
        : "=r"(a) : "l"(p));
    return a;
}
// 64B-row swizzle: row r (0..127), 16B slot h (0..3) — conflict-free per phase
__device__ __forceinline__ uint32_t sw64(int r, int h) {
    return (uint32_t)(r * 64 + ((h ^ ((r >> 1) & 3)) << 4));
}
// u-buffer rotation: row r (0..63), float column c (0..127) -> float index
__device__ __forceinline__ int urot(int c, int r) {
    return r * 128 + ((c + ((r & 31) << 2)) & 127);
}

#define CP16(dst, src) \
    asm volatile("cp.async.cg.shared.global [%0], [%1], 16;" \
                 :: "r"(dst), "l"(src))
#define CPCOMMIT() asm volatile("cp.async.commit_group;" ::: "memory")
#define CPWAIT(n)  asm volatile("cp.async.wait_group %0;" :: "n"(n) : "memory")

#define LDSM4(r0, r1, r2, r3, addr) \
    asm volatile("ldmatrix.sync.aligned.m8n8.x4.shared.b16 {%0,%1,%2,%3}, [%4];" \
                 : "=r"(r0), "=r"(r1), "=r"(r2), "=r"(r3) : "r"(addr))

#define MMA16816(d, a, b) \
    asm volatile("mma.sync.aligned.m16n8k16.row.col.f32.f16.f16.f32 " \
                 "{%0,%1,%2,%3}, {%4,%5,%6,%7}, {%8,%9}, {%0,%1,%2,%3};" \
                 : "+f"((d)[0]), "+f"((d)[1]), "+f"((d)[2]), "+f"((d)[3]) \
                 : "r"((a)[0]), "r"((a)[1]), "r"((a)[2]), "r"((a)[3]), \
                   "r"((b)[0]), "r"((b)[1]))

// LIF step. sneg carries -V_TH*s_prev in {0.0f, -1.0f}.
// spike: v > 1  <=>  signbit(1 - v); v==1 gives +0 -> no spike (strict >).
#define LIF_STEP(U)                                                           \
    {                                                                         \
        st_d = fmaf(c_beta, st_d, c_omb * (U));                               \
        st_v = fmaf(c_alpha, st_v, fmaf(c_oma, st_d, sneg));                  \
        sneg = __int_as_float((__float_as_int(1.0f - st_v) >> 31)             \
                              & 0xBF800000);                                  \
    }

__global__ __launch_bounds__(256, 2)
void gemm_lif_kernel(const float* __restrict__ v0,
                     const float* __restrict__ tau_n,
                     const float* __restrict__ tau_m,
                     const float* __restrict__ Wout,
                     const float* __restrict__ bout,
                     float* __restrict__ out) {
    extern __shared__ char smem[];
    const uint32_t sb = smem_u32(smem);

    const int tid  = threadIdx.x;
    const int wid  = tid >> 5;
    const int lane = tid & 31;
    const int n0 = blockIdx.x * 128;   // h-tile (8) — fast dim: CTAs share x[b] in L2
    const int b  = blockIdx.y;         // batch (256)

    const int wm_off = (wid & 1) * 64;
    const int wn_off = (wid >> 1) * 32;

    // ---- persistent LIF state (threads 0..127; one h column each) ----
    float st_d = 0.f, st_v = 0.f, sneg = 0.f, st_acc = 0.f;
    float c_beta = 0.f, c_omb = 0.f, c_alpha = 0.f, c_oma = 0.f;
    if (tid < 128) {
        const int hg = n0 + tid;
        c_beta  = 1.f / (1.f + expf(-tau_n[hg]));
        c_alpha = 1.f / (1.f + expf(-tau_m[hg]));
        c_omb   = 1.f - c_beta;
        c_oma   = 1.f - c_alpha;
        st_v    = v0[b * H_ + hg];
    }

    // cp.async mapping: 128 rows x 4 sixteen-byte slots per part, 2 units/thread
    const int ldr = tid >> 2;          // row 0..63 (unit 0); +64 for unit 1
    const int ldh = tid & 3;           // slot 0..3
    const uint32_t dst0 = sw64(ldr, ldh);           // unit 1: +4096
    const __half* pA0h = g_xh + (size_t)(b * T_ + ldr) * I_ + ldh * 8;
    const __half* pA0m = g_xm + (size_t)(b * T_ + ldr) * I_ + ldh * 8;
    const __half* pB0h = g_wh + (size_t)(n0 + ldr) * I_ + ldh * 8;
    const __half* pB0m = g_wm + (size_t)(n0 + ldr) * I_ + ldh * 8;

    const int arow = wm_off + (lane & 15);
    const int ahl  = (lane >> 4) & 1;               // k 16B-slot low bit
    const int brow = wn_off + (lane & 7) + ((lane >> 4) << 3);
    const int bhl  = (lane >> 3) & 1;

    const int g  = lane >> 2;
    const int tq = lane & 3;

    // issue one chunk's cp.asyncs: stage base + A/B element offsets
    auto load_at = [&](uint32_t base, size_t offA, int offB) {
        CP16(base + dst0,                         pA0h + offA);
        CP16(base + dst0 + 4096,                  pA0h + offA + (size_t)64 * I_);
        CP16(base + PART_BYTES + dst0,            pA0m + offA);
        CP16(base + PART_BYTES + dst0 + 4096,     pA0m + offA + (size_t)64 * I_);
        CP16(base + 2 * PART_BYTES + dst0,        pB0h + offB);
        CP16(base + 2 * PART_BYTES + dst0 + 4096, pB0h + offB + (size_t)64 * I_);
        CP16(base + 3 * PART_BYTES + dst0,        pB0m + offB);
        CP16(base + 3 * PART_BYTES + dst0 + 4096, pB0m + offB + (size_t)64 * I_);
    };

    // rotating stage bases: stA = current chunk, stB = +1, stC = +2 (prefetch dst)
    uint32_t stA = sb, stB = sb + STAGE_BYTES, stC = sb + 2 * STAGE_BYTES;

    load_at(stA, 0, 0);      CPCOMMIT();
    load_at(stB, KC, KC);    CPCOMMIT();

    // incremental prefetch offsets for chunk gc+2 (start: chunk 2)
    size_t offA_pf = 2 * KC;
    int    offB_pf = 2 * KC;

    float acc[4][4][4];
#pragma unroll
    for (int i = 0; i < 4; i++)
#pragma unroll
        for (int j = 0; j < 4; j++)
#pragma unroll
            for (int q = 0; q < 4; q++) acc[i][j][q] = 0.f;

    for (int gc = 0; gc < NGC; gc++) {
        if (gc < NGC - 1) { CPWAIT(1); } else { CPWAIT(0); }
        __syncthreads();
        if (gc + 2 < NGC) {
            load_at(stC, offA_pf, offB_pf);
            CPCOMMIT();
            // advance prefetch offsets to chunk gc+3
            if ((gc & 15) == 13) {          // (gc+3) enters a new t-tile
                offA_pf += (size_t)128 * I_ - 15 * KC;
                offB_pf = 0;
            } else {
                offA_pf += KC;
                offB_pf += KC;
            }
        }

        const uint32_t aBase = stA;
        const uint32_t bBase = stA + 2 * PART_BYTES;

#pragma unroll
        for (int kk2 = 0; kk2 < 2; kk2++) {         // two k16 sub-steps
            const int ha = kk2 * 2 + ahl;
            const int hb = kk2 * 2 + bhl;

            uint32_t bf[2][4][2];
#pragma unroll
            for (int p = 0; p < 2; p++)
#pragma unroll
                for (int j2 = 0; j2 < 2; j2++) {
                    uint32_t r0, r1, r2, r3;
                    LDSM4(r0, r1, r2, r3,
                          bBase + p * PART_BYTES + sw64(brow + 16 * j2, hb));
                    bf[p][2 * j2][0] = r0;     bf[p][2 * j2][1] = r1;
                    bf[p][2 * j2 + 1][0] = r2; bf[p][2 * j2 + 1][1] = r3;
                }

            // A high part: hh + hm (one A-part live at a time: no spills)
            {
                uint32_t af[4][4];
#pragma unroll
                for (int i = 0; i < 4; i++)
                    LDSM4(af[i][0], af[i][1], af[i][2], af[i][3],
                          aBase + sw64(arow + 16 * i, ha));
#pragma unroll
                for (int i = 0; i < 4; i++)
#pragma unroll
                    for (int j = 0; j < 4; j++)
                        MMA16816(acc[i][j], af[i], bf[0][j]);
#pragma unroll
                for (int i = 0; i < 4; i++)
#pragma unroll
                    for (int j = 0; j < 4; j++)
                        MMA16816(acc[i][j], af[i], bf[1][j]);
            }
            // A mid part: mh
            {
                uint32_t af[4][4];
#pragma unroll
                for (int i = 0; i < 4; i++)
                    LDSM4(af[i][0], af[i][1], af[i][2], af[i][3],
                          aBase + PART_BYTES + sw64(arow + 16 * i, ha));
#pragma unroll
                for (int i = 0; i < 4; i++)
#pragma unroll
                    for (int j = 0; j < 4; j++)
                        MMA16816(acc[i][j], af[i], bf[0][j]);
            }
        }

        // ---------------- tile boundary: dump + LIF in the freed stage -------
        if ((gc & 15) == 15) {
            const int mt = gc >> 4;      // boundary-only: cheap
            float* u_s = reinterpret_cast<float*>(smem + (stA - sb));

            __syncthreads();   // all warps done reading the freed stage

#pragma unroll
            for (int half = 0; half < 2; half++) {
                if (wm_off == half * 64) {
#pragma unroll
                    for (int i = 0; i < 4; i++)
#pragma unroll
                        for (int h2 = 0; h2 < 2; h2++) {
                            int r = 16 * i + 8 * h2 + g;        // row within half
#pragma unroll
                            for (int j = 0; j < 4; j++) {
                                int col = wn_off + 2 * tq + 8 * j;
                                float2 v = make_float2(acc[i][j][2 * h2],
                                                       acc[i][j][2 * h2 + 1]);
                                *reinterpret_cast<float2*>(u_s + urot(col, r)) = v;
                            }
                        }
                }
                __syncthreads();

                if (tid < 128) {
                    if (mt < 2) {
#pragma unroll 4
                        for (int tl = 0; tl < 64; tl++) {
                            float u = u_s[urot(tid, tl)];
                            LIF_STEP(u);
                        }
                    } else {
#pragma unroll 4
                        for (int tl = 0; tl < 64; tl++) {
                            float u = u_s[urot(tid, tl)];
                            LIF_STEP(u);
                            st_acc -= sneg;         // acc += s
                        }
                    }
                }
                __syncthreads();
            }

            // reset accumulators for the next t-tile
#pragma unroll
            for (int i = 0; i < 4; i++)
#pragma unroll
                for (int j = 0; j < 4; j++)
#pragma unroll
                    for (int q = 0; q < 4; q++) acc[i][j][q] = 0.f;
        }

        // rotate stage registers (cur <- next <- prefetch <- cur)
        uint32_t tmp = stA; stA = stB; stB = stC; stC = tmp;
    }

    // ---------------- fused output epilogue ----------------
    {
        float* sacc = reinterpret_cast<float*>(smem);
        if (tid < 128) sacc[tid] = st_acc;
        __syncthreads();
        if (tid < 128) {
            const float* wp = Wout + (size_t)n0 * O_ + tid;
            float sum = (blockIdx.x == 0) ? bout[tid] : 0.f;
#pragma unroll 8
            for (int h = 0; h < 128; h++)
                sum = fmaf(sacc[h], __ldg(wp + h * O_), sum);
            atomicAdd(out + b * O_ + tid, sum);
        }
    }
}

// ---------------------------------------------------------------------------
extern "C" void kernel_launch(void* const* d_in, const int* in_sizes, int n_in,
                              void* d_out, int out_size) {
    const float* x     = (const float*)d_in[0];
    const float* v0    = (const float*)d_in[1];
    const float* Wb    = (const float*)d_in[2];
    const float* tau_n = (const float*)d_in[3];
    const float* tau_m = (const float*)d_in[4];
    const float* Wout  = (const float*)d_in[5];
    const float* bout  = (const float*)d_in[6];
    float* out = (float*)d_out;
    (void)in_sizes; (void)n_in; (void)out_size;

    static bool attr_set = false;
    if (!attr_set) {
        cudaFuncSetAttribute(gemm_lif_kernel,
                             cudaFuncAttributeMaxDynamicSharedMemorySize,
                             SMEM_GEMM);
        attr_set = true;
    }

    prep_kernel<<<XBLKS + WBLKS + ZBLKS, 256>>>(x, Wb, out);   // launch 0

    dim3 ggrid(H_ / 128, B_);   // (8, 256)
    gemm_lif_kernel<<<ggrid, 256, SMEM_GEMM>>>(v0, tau_n, tau_m,
                                               Wout, bout, out);  // launch 1
}